// round 17
// baseline (speedup 1.0000x reference)
#include <cuda_runtime.h>
#include <cuda_bf16.h>
#include <math.h>
#include <stdint.h>

#define BB 4
#define NN 2048
#define CC 256
#define HH 16
#define DD 16
#define LOG2E 1.4426950408889634f

// ---------------------------------------------------------------------------
// Device scratch (allocation-free rule: __device__ globals)
// ---------------------------------------------------------------------------
__device__ unsigned short g_xh[(size_t)BB * NN * CC];   // x split planes [m][k]
__device__ unsigned short g_xl[(size_t)BB * NN * CC];
__device__ unsigned short g_wh[(size_t)3 * CC * CC];    // w_qkv^T split [n][k]
__device__ unsigned short g_wl[(size_t)3 * CC * CC];
__device__ unsigned short g_ph[(size_t)CC * CC];        // w_proj^T split [n][k]
__device__ unsigned short g_pl[(size_t)CC * CC];
// Q/K split-bf16: [bh][token][32] (d 0-15 = hi, 16-31 = lo). Q pre-scaled by log2e.
__device__ unsigned short g_qs[(size_t)BB * HH * NN * 32];
__device__ unsigned short g_ks[(size_t)BB * HH * NN * 32];
// V^T split-bf16: [bh][split(2)][d(16)][token]
__device__ unsigned short g_vts[(size_t)BB * HH * 32 * NN];
// attention output split planes, (B*N, C)
__device__ unsigned short g_oh[(size_t)BB * NN * CC];
__device__ unsigned short g_ol[(size_t)BB * NN * CC];

// ---------------------------------------------------------------------------
// Helpers
// ---------------------------------------------------------------------------
__device__ __forceinline__ void mma16816(float* d, const unsigned* a, const unsigned* b) {
    asm volatile(
        "mma.sync.aligned.m16n8k16.row.col.f32.bf16.bf16.f32 "
        "{%0,%1,%2,%3}, {%4,%5,%6,%7}, {%8,%9}, {%0,%1,%2,%3};"
        : "+f"(d[0]), "+f"(d[1]), "+f"(d[2]), "+f"(d[3])
        : "r"(a[0]), "r"(a[1]), "r"(a[2]), "r"(a[3]), "r"(b[0]), "r"(b[1]));
}
__device__ __forceinline__ unsigned pk2cvt(float e0, float e1) {  // lo half = e0
    unsigned r;
    asm("cvt.rn.bf16x2.f32 %0, %1, %2;" : "=r"(r) : "f"(e1), "f"(e0));
    return r;
}
__device__ __forceinline__ float lo_bf(unsigned p) { return __uint_as_float(p << 16); }
__device__ __forceinline__ float hi_bf(unsigned p) { return __uint_as_float(p & 0xFFFF0000u); }
__device__ __forceinline__ float ex2f(float x) {
    float r;
    asm("ex2.approx.f32 %0, %1;" : "=f"(r) : "f"(x));
    return r;
}

// ---------------------------------------------------------------------------
// Conversion kernels: fp32 -> split bf16 hi/lo
// ---------------------------------------------------------------------------
__global__ void convert_x_kernel(const float* __restrict__ x) {
    int i = blockIdx.x * 256 + threadIdx.x;
    float v = x[i];
    unsigned hu = (unsigned)__bfloat16_as_ushort(__float2bfloat16_rn(v));
    float res = v - __uint_as_float(hu << 16);
    g_xh[i] = (unsigned short)hu;
    g_xl[i] = __bfloat16_as_ushort(__float2bfloat16_rn(res));
}
__global__ void convert_w_kernel(const float* __restrict__ w) {
    int idx = blockIdx.x * 256 + threadIdx.x;  // 196608 = 768*256
    int n = idx >> 8, k = idx & 255;
    float v = w[(size_t)k * (3 * CC) + n];
    unsigned hu = (unsigned)__bfloat16_as_ushort(__float2bfloat16_rn(v));
    float res = v - __uint_as_float(hu << 16);
    g_wh[idx] = (unsigned short)hu;
    g_wl[idx] = __bfloat16_as_ushort(__float2bfloat16_rn(res));
}
__global__ void convert_wp_kernel(const float* __restrict__ w) {
    int idx = blockIdx.x * 256 + threadIdx.x;  // 65536 = 256*256
    int n = idx >> 8, k = idx & 255;
    float v = w[(size_t)k * CC + n];
    unsigned hu = (unsigned)__bfloat16_as_ushort(__float2bfloat16_rn(v));
    float res = v - __uint_as_float(hu << 16);
    g_ph[idx] = (unsigned short)hu;
    g_pl[idx] = __bfloat16_as_ushort(__float2bfloat16_rn(res));
}

// ---------------------------------------------------------------------------
// QKV GEMM via HMMA: tile M=128 x N=64, 256 threads (8 warps, 16 rows/warp).
// 3-term split: Ah*Bh + Ah*Bl + Al*Bh. Epilogue scatters split-bf16 q/k/v.
// ---------------------------------------------------------------------------
__global__ __launch_bounds__(256) void gemm_qkv_hmma(const float* __restrict__ bias) {
    __shared__ __align__(16) unsigned short sA[128 * 40];
    __shared__ __align__(16) unsigned short sB[64 * 40];
    int tid = threadIdx.x;
    int w = tid >> 5, lane = tid & 31;
    int g = lane >> 2, t = lane & 3;
    int m0 = blockIdx.y * 128, n0 = blockIdx.x * 64;

    const unsigned* sAw = (const unsigned*)sA;
    const unsigned* sBw = (const unsigned*)sB;

    float acc[8][4] = {};

    for (int kc = 0; kc < 16; kc++) {
        int k0 = kc * 16;
        __syncthreads();
        // A: 128 rows, each thread loads half a row (hi or lo plane)
        {
            int row = tid >> 1, seg = tid & 1;
            const uint4* src = (const uint4*)((seg ? g_xl : g_xh) + (size_t)(m0 + row) * CC + k0);
            uint4* d = (uint4*)(sA + row * 40 + seg * 16);
            d[0] = src[0]; d[1] = src[1];
        }
        // B: 64 n-rows (threads 0..127)
        if (tid < 128) {
            int brow = tid >> 1, bseg = tid & 1;
            const uint4* src = (const uint4*)((bseg ? g_wl : g_wh) + (size_t)(n0 + brow) * CC + k0);
            uint4* d = (uint4*)(sB + brow * 40 + bseg * 16);
            d[0] = src[0]; d[1] = src[1];
        }
        __syncthreads();

        unsigned ah[4], al[4];
        {
            int r0 = w * 16 + g;
            int w0 = r0 * 20, w8 = (r0 + 8) * 20;
            ah[0] = sAw[w0 + t];      ah[1] = sAw[w8 + t];
            ah[2] = sAw[w0 + t + 4];  ah[3] = sAw[w8 + t + 4];
            al[0] = sAw[w0 + t + 8];  al[1] = sAw[w8 + t + 8];
            al[2] = sAw[w0 + t + 12]; al[3] = sAw[w8 + t + 12];
        }
#pragma unroll
        for (int nt = 0; nt < 8; nt++) {
            int wb = (nt * 8 + g) * 20;
            unsigned bh[2], bl[2];
            bh[0] = sBw[wb + t];     bh[1] = sBw[wb + t + 4];
            bl[0] = sBw[wb + t + 8]; bl[1] = sBw[wb + t + 12];
            mma16816(acc[nt], ah, bh);
            mma16816(acc[nt], ah, bl);
            mma16816(acc[nt], al, bh);
        }
    }

    // Epilogue: scatter split-bf16 into g_qs/g_ks/g_vts (Q scaled by log2e)
#pragma unroll
    for (int rr = 0; rr < 2; rr++) {
        int m = m0 + w * 16 + g + rr * 8;
        int b = m >> 11, nq = m & 2047;
#pragma unroll
        for (int nt = 0; nt < 8; nt++) {
            int n = n0 + nt * 8 + 2 * t;          // even
            float v0 = acc[nt][rr * 2 + 0] + bias[n];
            float v1 = acc[nt][rr * 2 + 1] + bias[n + 1];
            int ty = n >> 8, rem = n & 255;
            int h = rem >> 4, d = rem & 15;       // d even; pair is d, d+1
            int bhh = b * HH + h;
            if (ty == 0) { v0 *= LOG2E; v1 *= LOG2E; }
            unsigned hp = pk2cvt(v0, v1);
            unsigned lp = pk2cvt(v0 - lo_bf(hp), v1 - hi_bf(hp));
            if (ty < 2) {
                unsigned short* dst = (ty == 0) ? g_qs : g_ks;
                size_t base = ((size_t)bhh * NN + nq) * 32 + d;
                *(unsigned*)&dst[base]      = hp;
                *(unsigned*)&dst[base + 16] = lp;
            } else {
                size_t base = ((size_t)bhh * 32 + d) * NN + nq;
                g_vts[base]                     = (unsigned short)(hp & 0xFFFF);
                g_vts[base + NN]                = (unsigned short)(hp >> 16);
                g_vts[base + (size_t)16 * NN]   = (unsigned short)(lp & 0xFFFF);
                g_vts[base + (size_t)17 * NN]   = (unsigned short)(lp >> 16);
            }
        }
    }
}

// ---------------------------------------------------------------------------
// Proj GEMM via HMMA: A = split O planes, B = split w_proj^T. fp32 out.
// Tile M=128 x N=64, 256 threads, same structure as qkv.
// ---------------------------------------------------------------------------
__global__ __launch_bounds__(256) void gemm_proj_hmma(const float* __restrict__ bias,
                                                      float* __restrict__ out) {
    __shared__ __align__(16) unsigned short sA[128 * 40];
    __shared__ __align__(16) unsigned short sB[64 * 40];
    int tid = threadIdx.x;
    int w = tid >> 5, lane = tid & 31;
    int g = lane >> 2, t = lane & 3;
    int m0 = blockIdx.y * 128, n0 = blockIdx.x * 64;

    const unsigned* sAw = (const unsigned*)sA;
    const unsigned* sBw = (const unsigned*)sB;

    float acc[8][4] = {};

    for (int kc = 0; kc < 16; kc++) {
        int k0 = kc * 16;
        __syncthreads();
        {
            int row = tid >> 1, seg = tid & 1;
            const uint4* src = (const uint4*)((seg ? g_ol : g_oh) + (size_t)(m0 + row) * CC + k0);
            uint4* d = (uint4*)(sA + row * 40 + seg * 16);
            d[0] = src[0]; d[1] = src[1];
        }
        if (tid < 128) {
            int brow = tid >> 1, bseg = tid & 1;
            const uint4* src = (const uint4*)((bseg ? g_pl : g_ph) + (size_t)(n0 + brow) * CC + k0);
            uint4* d = (uint4*)(sB + brow * 40 + bseg * 16);
            d[0] = src[0]; d[1] = src[1];
        }
        __syncthreads();

        unsigned ah[4], al[4];
        {
            int r0 = w * 16 + g;
            int w0 = r0 * 20, w8 = (r0 + 8) * 20;
            ah[0] = sAw[w0 + t];      ah[1] = sAw[w8 + t];
            ah[2] = sAw[w0 + t + 4];  ah[3] = sAw[w8 + t + 4];
            al[0] = sAw[w0 + t + 8];  al[1] = sAw[w8 + t + 8];
            al[2] = sAw[w0 + t + 12]; al[3] = sAw[w8 + t + 12];
        }
#pragma unroll
        for (int nt = 0; nt < 8; nt++) {
            int wb = (nt * 8 + g) * 20;
            unsigned bh[2], bl[2];
            bh[0] = sBw[wb + t];     bh[1] = sBw[wb + t + 4];
            bl[0] = sBw[wb + t + 8]; bl[1] = sBw[wb + t + 12];
            mma16816(acc[nt], ah, bh);
            mma16816(acc[nt], ah, bl);
            mma16816(acc[nt], al, bh);
        }
    }

#pragma unroll
    for (int rr = 0; rr < 2; rr++) {
        int m = m0 + w * 16 + g + rr * 8;
#pragma unroll
        for (int nt = 0; nt < 8; nt++) {
            int n = n0 + nt * 8 + 2 * t;
            float2 v = make_float2(acc[nt][rr * 2 + 0] + bias[n],
                                   acc[nt][rr * 2 + 1] + bias[n + 1]);
            *(float2*)&out[(size_t)m * CC + n] = v;
        }
    }
}

// ---------------------------------------------------------------------------
// HMMA flash attention: 256 threads (8 warps, 16 q-rows/warp).
// Q pre-scaled by log2e; p = ex2(s). Split-bf16 O epilogue for proj HMMA.
// ---------------------------------------------------------------------------
#define QROW 40
#define VROW 136

__global__ __launch_bounds__(256) void attn_hmma_kernel() {
    __shared__ __align__(16) unsigned short sQ[128 * QROW];
    __shared__ __align__(16) unsigned short sK[128 * QROW];
    __shared__ __align__(16) unsigned short sVt[32 * VROW];

    int tid = threadIdx.x;
    int w = tid >> 5, lane = tid & 31;
    int g = lane >> 2, t = lane & 3;
    int bh = blockIdx.y, q0 = blockIdx.x * 128;

    // Q tile: each thread loads half a row
    {
        int row = tid >> 1, seg = tid & 1;
        const uint4* src = (const uint4*)(g_qs + ((size_t)bh * NN + q0 + row) * 32 + seg * 16);
        uint4* d = (uint4*)(sQ + row * QROW + seg * 16);
        d[0] = src[0]; d[1] = src[1];
    }
    __syncthreads();

    const unsigned* sQw = (const unsigned*)sQ;
    const unsigned* sKw = (const unsigned*)sK;
    const unsigned* sVw = (const unsigned*)sVt;
    unsigned qh[4], ql[4];
    {
        int r0 = w * 16 + g;
        int w0 = r0 * (QROW / 2), w8 = (r0 + 8) * (QROW / 2);
        qh[0] = sQw[w0 + t];      qh[1] = sQw[w8 + t];
        qh[2] = sQw[w0 + t + 4];  qh[3] = sQw[w8 + t + 4];
        ql[0] = sQw[w0 + t + 8];  ql[1] = sQw[w8 + t + 8];
        ql[2] = sQw[w0 + t + 12]; ql[3] = sQw[w8 + t + 12];
    }

    float o[2][4] = {};
    float l[2] = {};

    for (int j = 0; j < 16; j++) {
        int k0 = j * 128;
        __syncthreads();
        // K tile
        {
            int row = tid >> 1, seg = tid & 1;
            const uint4* src = (const uint4*)(g_ks + ((size_t)bh * NN + k0 + row) * 32 + seg * 16);
            uint4* d = (uint4*)(sK + row * QROW + seg * 16);
            d[0] = src[0]; d[1] = src[1];
        }
        // V^T tiles: 32 rows x 128 keys, each thread 16 keys
        {
            int row = tid >> 3, part = tid & 7;
            const uint4* src = (const uint4*)(g_vts + ((size_t)bh * 32 + row) * NN + k0 + part * 16);
            uint4* d = (uint4*)(sVt + row * VROW + part * 16);
            d[0] = src[0]; d[1] = src[1];
        }
        __syncthreads();

        for (int kc = 0; kc < 8; kc++) {
            unsigned kh[2][2], kl[2][2];
#pragma unroll
            for (int nt = 0; nt < 2; nt++) {
                int wk = (kc * 16 + nt * 8 + g) * (QROW / 2);
                kh[nt][0] = sKw[wk + t];     kh[nt][1] = sKw[wk + t + 4];
                kl[nt][0] = sKw[wk + t + 8]; kl[nt][1] = sKw[wk + t + 12];
            }
            unsigned vh[2][2], vl[2][2];
#pragma unroll
            for (int dt = 0; dt < 2; dt++) {
                int bhw = (dt * 8 + g) * (VROW / 2) + kc * 8 + t;
                int blw = (16 + dt * 8 + g) * (VROW / 2) + kc * 8 + t;
                vh[dt][0] = sVw[bhw]; vh[dt][1] = sVw[bhw + 4];
                vl[dt][0] = sVw[blw]; vl[dt][1] = sVw[blw + 4];
            }
            float s0[4] = {}, s1[4] = {};
            mma16816(s0, qh, kh[0]);
            mma16816(s0, qh, kl[0]);
            mma16816(s0, ql, kh[0]);
            mma16816(s1, qh, kh[1]);
            mma16816(s1, qh, kl[1]);
            mma16816(s1, ql, kh[1]);
            float e00 = ex2f(s0[0]), e01 = ex2f(s0[1]);
            float e02 = ex2f(s0[2]), e03 = ex2f(s0[3]);
            float e10 = ex2f(s1[0]), e11 = ex2f(s1[1]);
            float e12 = ex2f(s1[2]), e13 = ex2f(s1[3]);
            l[0] += e00 + e01 + e10 + e11;
            l[1] += e02 + e03 + e12 + e13;
            unsigned ph[4], pl[4];
            ph[0] = pk2cvt(e00, e01);
            pl[0] = pk2cvt(e00 - lo_bf(ph[0]), e01 - hi_bf(ph[0]));
            ph[1] = pk2cvt(e02, e03);
            pl[1] = pk2cvt(e02 - lo_bf(ph[1]), e03 - hi_bf(ph[1]));
            ph[2] = pk2cvt(e10, e11);
            pl[2] = pk2cvt(e10 - lo_bf(ph[2]), e11 - hi_bf(ph[2]));
            ph[3] = pk2cvt(e12, e13);
            pl[3] = pk2cvt(e12 - lo_bf(ph[3]), e13 - hi_bf(ph[3]));
#pragma unroll
            for (int dt = 0; dt < 2; dt++) {
                mma16816(o[dt], ph, vh[dt]);
                mma16816(o[dt], ph, vl[dt]);
                mma16816(o[dt], pl, vh[dt]);
            }
        }
    }

#pragma unroll
    for (int i = 0; i < 2; i++) {
        l[i] += __shfl_xor_sync(0xFFFFFFFFu, l[i], 1);
        l[i] += __shfl_xor_sync(0xFFFFFFFFu, l[i], 2);
    }

    // Epilogue: O/l -> split bf16 planes (B*N, C)
    int b = bh >> 4, h = bh & 15;
    float inv0 = 1.0f / l[0];
    float inv1 = 1.0f / l[1];
    int row0 = q0 + w * 16 + g;
#pragma unroll
    for (int dt = 0; dt < 2; dt++) {
        int col = h * 16 + dt * 8 + 2 * t;
        {
            float v0 = o[dt][0] * inv0, v1 = o[dt][1] * inv0;
            unsigned hp = pk2cvt(v0, v1);
            unsigned lp = pk2cvt(v0 - lo_bf(hp), v1 - hi_bf(hp));
            size_t idx = ((size_t)(b * NN) + row0) * CC + col;
            *(unsigned*)&g_oh[idx] = hp;
            *(unsigned*)&g_ol[idx] = lp;
        }
        {
            float v0 = o[dt][2] * inv1, v1 = o[dt][3] * inv1;
            unsigned hp = pk2cvt(v0, v1);
            unsigned lp = pk2cvt(v0 - lo_bf(hp), v1 - hi_bf(hp));
            size_t idx = ((size_t)(b * NN) + row0 + 8) * CC + col;
            *(unsigned*)&g_oh[idx] = hp;
            *(unsigned*)&g_ol[idx] = lp;
        }
    }
}

// ---------------------------------------------------------------------------
extern "C" void kernel_launch(void* const* d_in, const int* in_sizes, int n_in,
                              void* d_out, int out_size) {
    const float* x      = (const float*)d_in[0];
    const float* w_qkv  = (const float*)d_in[1];
    const float* b_qkv  = (const float*)d_in[2];
    const float* w_proj = (const float*)d_in[3];
    const float* b_proj = (const float*)d_in[4];
    float* out = (float*)d_out;

    convert_x_kernel<<<BB * NN * CC / 256, 256>>>(x);
    convert_w_kernel<<<3 * CC * CC / 256, 256>>>(w_qkv);
    convert_wp_kernel<<<CC * CC / 256, 256>>>(w_proj);

    dim3 g1(12, 64);               // 768/64 n-tiles, 8192/128 m-tiles
    gemm_qkv_hmma<<<g1, 256>>>(b_qkv);

    dim3 g2(NN / 128, BB * HH);    // (16, 64)
    attn_hmma_kernel<<<g2, 256>>>();

    dim3 g3(4, 64);                // 256/64, 8192/128
    gemm_proj_hmma<<<g3, 256>>>(b_proj, out);
}